// round 1
// baseline (speedup 1.0000x reference)
#include <cuda_runtime.h>
#include <cstdint>
#include <cstddef>

#define NB 4
#define NN 2048
#define NCTA 128
#define TPB 512
#define WPC 16
#define TC 4
#define NITS_K 50

// constants (log2-domain Sinkhorn)
constexpr float C_EPS   = 0.1f;
constexpr float C_TOL   = 1e-3f;
constexpr float C_ALPHA = -1.3862943611198906f;   // ln(1/4)  (weights are 1/batch_size)
constexpr float C_L2E   = 1.4426950408889634f;    // log2(e)
constexpr float C_KK    = C_L2E / C_EPS;          // log2(e)/eps
constexpr float C_2K    = 2.0f * C_KK;
constexpr float C_INVK  = C_EPS / C_L2E;          // 1/C_KK = eps*ln2
constexpr float C_LN2   = 0.6931471805599453f;

struct ScratchT {
    unsigned barcnt;
    unsigned pad[31];
    float A1[NB * NN];
    float B1[NB * NN];
    float A2[NB * NN];
    float B2[NB * NN];
    float errA[2 * NITS_K * NB];
    float errB[2 * NITS_K * NB];
    float cost[2 * NB];
    float cham[2 * NB];
};
__device__ ScratchT g_s;

__device__ __forceinline__ float ex2f_(float x) {
    float y;
    asm("ex2.approx.ftz.f32 %0, %1;" : "=f"(y) : "f"(x));
    return y;
}
__device__ __forceinline__ float lg2f_(float x) {
    float y;
    asm("lg2.approx.f32 %0, %1;" : "=f"(y) : "f"(x));
    return y;
}

// Software grid barrier: monotonic counter, release-RED arrive, acquire-LD spin.
// All 128 CTAs are co-resident (<=1-2 per SM), so this cannot deadlock.
__device__ __forceinline__ void grid_barrier(unsigned& lb) {
    __syncthreads();
    lb++;
    if (threadIdx.x == 0) {
        unsigned target = lb * (unsigned)NCTA;
        asm volatile("red.release.gpu.global.add.u32 [%0], %1;"
                     :: "l"(&g_s.barcnt), "r"(1u) : "memory");
        unsigned v;
        while (true) {
            asm volatile("ld.acquire.gpu.global.u32 %0, [%1];"
                         : "=r"(v) : "l"(&g_s.barcnt) : "memory");
            if (v >= target) break;
            __nanosleep(128);
        }
    }
    __syncthreads();
}

// One Sinkhorn half-update in log2 domain:
//   dst[j] = -ln2 * ( c_j + m_j + log2( sum_i 2^(w_ij - m_j) ) )
//   w_ij = u_i + 2k*(r_i . q_j),  u_i = (src_i + alpha)*log2e - k*|r_i|^2,  c_j = -k*|q_j|^2
// sR: points of summed dim (smem), sQ: points of output dim (smem).
__device__ __forceinline__ void half_update(
    const float4* __restrict__ sR, const float4* __restrict__ sQ,
    float* __restrict__ sU,
    const float* __restrict__ src, float* __restrict__ dst,
    float* errslot, int slot)
{
    const int tid = threadIdx.x;
    for (int t = tid; t < NN; t += TPB) {
        float s  = __ldcg(src + t);
        float4 r = sR[t];
        sU[t] = fmaf(s + C_ALPHA, C_L2E, -C_KK * r.w);
    }
    __syncthreads();

    const int wid = tid >> 5, lane = tid & 31;
    const int j0 = (slot * WPC + wid) * TC;

    float qx[TC], qy[TC], qz[TC], cj[TC];
#pragma unroll
    for (int t = 0; t < TC; t++) {
        float4 q = sQ[j0 + t];
        qx[t] = q.x * C_2K; qy[t] = q.y * C_2K; qz[t] = q.z * C_2K;
        cj[t] = -C_KK * q.w;
    }

    // pass 1: column maxes
    float m[TC];
#pragma unroll
    for (int t = 0; t < TC; t++) m[t] = -3.4e38f;
#pragma unroll 2
    for (int i = lane; i < NN; i += 32) {
        float4 g = sR[i];
        float  u = sU[i];
#pragma unroll
        for (int t = 0; t < TC; t++) {
            float w = fmaf(g.x, qx[t], fmaf(g.y, qy[t], fmaf(g.z, qz[t], u)));
            m[t] = fmaxf(m[t], w);
        }
    }
#pragma unroll
    for (int o = 16; o > 0; o >>= 1)
#pragma unroll
        for (int t = 0; t < TC; t++)
            m[t] = fmaxf(m[t], __shfl_xor_sync(0xffffffffu, m[t], o));

    // pass 2: shifted exp sums
    float sa[TC];
#pragma unroll
    for (int t = 0; t < TC; t++) sa[t] = 0.f;
#pragma unroll 2
    for (int i = lane; i < NN; i += 32) {
        float4 g = sR[i];
        float  u = sU[i];
#pragma unroll
        for (int t = 0; t < TC; t++) {
            float w = fmaf(g.x, qx[t], fmaf(g.y, qy[t], fmaf(g.z, qz[t], u)));
            sa[t] += ex2f_(w - m[t]);
        }
    }
#pragma unroll
    for (int o = 16; o > 0; o >>= 1)
#pragma unroll
        for (int t = 0; t < TC; t++)
            sa[t] += __shfl_xor_sync(0xffffffffu, sa[t], o);

    if (lane == 0) {
        float esum = 0.f;
#pragma unroll
        for (int t = 0; t < TC; t++) {
            float lse2 = cj[t] + m[t] + lg2f_(sa[t]);
            float nv = -C_LN2 * lse2;
            float ov = __ldcg(dst + j0 + t);
            esum += fabsf(nv - ov);
            __stcg(dst + j0 + t, nv);
        }
        atomicAdd(errslot, esum);
    }
    __syncthreads();
}

// cost = sum_ij exp(A_j + B_i - C_ij/eps) * C_ij (accumulated; /(n*m) applied at end)
__device__ __forceinline__ void cost_pass(
    const float4* __restrict__ sR, const float4* __restrict__ sQ,
    float* __restrict__ sU,
    const float* __restrict__ srcRow, const float* __restrict__ srcCol,
    float* costslot, int slot)
{
    const int tid = threadIdx.x;
    for (int t = tid; t < NN; t += TPB) {
        float s  = __ldcg(srcRow + t);
        float4 r = sR[t];
        sU[t] = fmaf(s, C_L2E, -C_KK * r.w);
    }
    __syncthreads();

    const int wid = tid >> 5, lane = tid & 31;
    const int j0 = (slot * WPC + wid) * TC;

    float qx[TC], qy[TC], qz[TC], cp[TC], qw[TC];
#pragma unroll
    for (int t = 0; t < TC; t++) {
        float4 q = sQ[j0 + t];
        qx[t] = q.x * C_2K; qy[t] = q.y * C_2K; qz[t] = q.z * C_2K;
        qw[t] = q.w;
        float a = __ldcg(srcCol + j0 + t);
        cp[t] = fmaf(a, C_L2E, -C_KK * q.w);
    }

    float a1[TC], a2[TC];
#pragma unroll
    for (int t = 0; t < TC; t++) { a1[t] = 0.f; a2[t] = 0.f; }
#pragma unroll 2
    for (int i = lane; i < NN; i += 32) {
        float4 g = sR[i];
        float  u = sU[i];
#pragma unroll
        for (int t = 0; t < TC; t++) {
            float w = fmaf(g.x, qx[t], fmaf(g.y, qy[t], fmaf(g.z, qz[t], u)));
            float e = ex2f_(w + cp[t]);                  // <= exp(-alpha)=4, no overflow
            float X = fmaf(u - w, C_INVK, g.w);          // C_ij = X + |q_j|^2
            a1[t] = fmaf(e, X, a1[t]);
            a2[t] += e;
        }
    }
#pragma unroll
    for (int o = 16; o > 0; o >>= 1)
#pragma unroll
        for (int t = 0; t < TC; t++) {
            a1[t] += __shfl_xor_sync(0xffffffffu, a1[t], o);
            a2[t] += __shfl_xor_sync(0xffffffffu, a2[t], o);
        }
    if (lane == 0) {
        float v = 0.f;
#pragma unroll
        for (int t = 0; t < TC; t++) v += a1[t] + qw[t] * a2[t];
        atomicAdd(costslot, v);
    }
    __syncthreads();
}

// chamfer: per own-point j, min over iter-points i of |g_i - q_j|^2; accumulate sum of mins
__device__ __forceinline__ void cham_pass(
    const float4* __restrict__ sIter, const float4* __restrict__ sOwn,
    float* accum, int slot)
{
    const int tid = threadIdx.x, wid = tid >> 5, lane = tid & 31;
    const int j0 = (slot * WPC + wid) * TC;
    float qx[TC], qy[TC], qz[TC], qw[TC], m[TC];
#pragma unroll
    for (int t = 0; t < TC; t++) {
        float4 q = sOwn[j0 + t];
        qx[t] = -2.f * q.x; qy[t] = -2.f * q.y; qz[t] = -2.f * q.z;
        qw[t] = q.w;
        m[t] = 3.4e38f;
    }
#pragma unroll 2
    for (int i = lane; i < NN; i += 32) {
        float4 g = sIter[i];
#pragma unroll
        for (int t = 0; t < TC; t++) {
            float v = fmaf(g.x, qx[t], fmaf(g.y, qy[t], fmaf(g.z, qz[t], g.w)));
            m[t] = fminf(m[t], v);
        }
    }
#pragma unroll
    for (int o = 16; o > 0; o >>= 1)
#pragma unroll
        for (int t = 0; t < TC; t++)
            m[t] = fminf(m[t], __shfl_xor_sync(0xffffffffu, m[t], o));
    if (lane == 0) {
        float s = 0.f;
#pragma unroll
        for (int t = 0; t < TC; t++) s += m[t] + qw[t];
        atomicAdd(accum, s);
    }
}

__device__ __forceinline__ void run_sink(
    const float4* sRow, const float4* sCol, float* sU,
    float* A, float* Bv, int erroff, float* costslot, int b, int slot, unsigned& lb)
{
    int it = 0;
    bool cont = true;
    while (cont) {
        half_update(sRow, sCol, sU, Bv, A, &g_s.errA[erroff + it * NB + b], slot);
        grid_barrier(lb);
        half_update(sCol, sRow, sU, A, Bv, &g_s.errB[erroff + it * NB + b], slot);
        grid_barrier(lb);
        float ae = 0.f, be = 0.f;
#pragma unroll
        for (int bb = 0; bb < NB; bb++) {
            ae = fmaxf(ae, __ldcg(&g_s.errA[erroff + it * NB + bb]));
            be = fmaxf(be, __ldcg(&g_s.errB[erroff + it * NB + bb]));
        }
        ae *= (C_EPS / (float)NN);
        be *= (C_EPS / (float)NN);
        it++;
        cont = (it < NITS_K) && (ae >= C_TOL || be >= C_TOL);
    }
    cost_pass(sRow, sCol, sU, Bv, A, costslot, slot);
}

__global__ void __launch_bounds__(TPB, 1)
emd_kernel(const float* __restrict__ preds, const float* __restrict__ gts,
           float* __restrict__ out, int out_size)
{
    extern __shared__ float4 smem4[];
    float4* sG = smem4;                 // gts points of this batch (x,y,z,|.|^2)
    float4* sP = smem4 + NN;            // preds points
    float*  sU = (float*)(smem4 + 2 * NN);

    const int b = blockIdx.x >> 5;
    const int slot = blockIdx.x & 31;

    const float* gp = gts + (size_t)b * NN * 3;
    const float* pp = preds + (size_t)b * NN * 3;
    for (int i = threadIdx.x; i < NN; i += TPB) {
        float x = gp[3 * i + 0], y = gp[3 * i + 1], z = gp[3 * i + 2];
        sG[i] = make_float4(x, y, z, fmaf(x, x, fmaf(y, y, z * z)));
        x = pp[3 * i + 0]; y = pp[3 * i + 1]; z = pp[3 * i + 2];
        sP[i] = make_float4(x, y, z, fmaf(x, x, fmaf(y, y, z * z)));
    }
    __syncthreads();

    unsigned lb = 0;

    // Chamfer: col-mins (min over gts per pred) and row-mins (min over preds per gt)
    cham_pass(sG, sP, &g_s.cham[b], slot);
    cham_pass(sP, sG, &g_s.cham[NB + b], slot);

    // Sinkhorn run 1: C(gts, preds); A indexes preds, B indexes gts
    run_sink(sG, sP, sU, g_s.A1 + b * NN, g_s.B1 + b * NN,
             0, &g_s.cost[b], b, slot, lb);

    // Sinkhorn run 2: C(preds, preds)
    run_sink(sP, sP, sU, g_s.A2 + b * NN, g_s.B2 + b * NN,
             NITS_K * NB, &g_s.cost[NB + b], b, slot, lb);

    grid_barrier(lb);

    if (blockIdx.x == 0 && threadIdx.x == 0) {
        const float inv_nm = 1.0f / ((float)NN * (float)NN);
        for (int bb = 0; bb < NB && bb < out_size; bb++) {
            float c1 = __ldcg(&g_s.cost[bb]);
            float c2 = __ldcg(&g_s.cost[NB + bb]);
            out[bb] = (c1 - 0.5f * c2) * inv_nm;
        }
        if (out_size >= 5) {
            float ch = 0.f;
            for (int bb = 0; bb < NB; bb++)
                ch += __ldcg(&g_s.cham[bb]) + __ldcg(&g_s.cham[NB + bb]);
            out[4] = ch / (float)(NB * NN);
        }
    }
}

extern "C" void kernel_launch(void* const* d_in, const int* in_sizes, int n_in,
                              void* d_out, int out_size)
{
    const float* preds = (const float*)d_in[0];
    const float* gts   = (const float*)d_in[1];
    float* out = (float*)d_out;

    void* sptr = nullptr;
    cudaGetSymbolAddress(&sptr, g_s);
    cudaMemsetAsync(sptr, 0, sizeof(ScratchT), 0);

    const int smem = (int)(2 * NN * sizeof(float4) + NN * sizeof(float));
    cudaFuncSetAttribute(emd_kernel, cudaFuncAttributeMaxDynamicSharedMemorySize, smem);
    emd_kernel<<<NCTA, TPB, smem, 0>>>(preds, gts, out, out_size);
}

// round 2
// speedup vs baseline: 1.0761x; 1.0761x over previous
#include <cuda_runtime.h>
#include <cstdint>
#include <cstddef>

#define NB 4
#define NN 2048
#define NCTA 256
#define TPB 512
#define WPC 16
#define TC 2
#define NITS_K 50

// constants (log2-domain Sinkhorn)
constexpr float C_EPS   = 0.1f;
constexpr float C_TOL   = 1e-3f;
constexpr float C_ALPHA = -1.3862943611198906f;   // ln(1/4)
constexpr float C_L2E   = 1.4426950408889634f;    // log2(e)
constexpr float C_KK    = C_L2E / C_EPS;          // log2(e)/eps
constexpr float C_2K    = 2.0f * C_KK;
constexpr float C_INVK  = C_EPS / C_L2E;
constexpr float C_LN2   = 0.6931471805599453f;

struct ScratchT {
    unsigned barcnt;
    unsigned pad[31];
    float A1[NB * NN];
    float B1[NB * NN];
    float A2[NB * NN];
    float B2[NB * NN];
    float errA[2 * NITS_K * NB];
    float errB[2 * NITS_K * NB];
    float cost[2 * NB];
    float cham[2 * NB];
};
__device__ ScratchT g_s;

__device__ __forceinline__ float ex2f_(float x) {
    float y; asm("ex2.approx.ftz.f32 %0, %1;" : "=f"(y) : "f"(x)); return y;
}
__device__ __forceinline__ float lg2f_(float x) {
    float y; asm("lg2.approx.f32 %0, %1;" : "=f"(y) : "f"(x)); return y;
}

// Software grid barrier: all 256 CTAs co-resident (2/SM guaranteed by
// __launch_bounds__(512,2) + 74KB smem/CTA), so this cannot deadlock.
__device__ __forceinline__ void grid_barrier(unsigned& lb) {
    __syncthreads();
    lb++;
    if (threadIdx.x == 0) {
        unsigned target = lb * (unsigned)NCTA;
        asm volatile("red.release.gpu.global.add.u32 [%0], %1;"
                     :: "l"(&g_s.barcnt), "r"(1u) : "memory");
        unsigned v;
        while (true) {
            asm volatile("ld.acquire.gpu.global.u32 %0, [%1];"
                         : "=r"(v) : "l"(&g_s.barcnt) : "memory");
            if (v >= target) break;
            __nanosleep(64);
        }
    }
    __syncthreads();
}

// One Sinkhorn half-update, single pass (no max sweep):
//   analytic bound m_j = Mv + k|q_j|^2  with Mv = max_i (src_i+alpha)*log2e
//   guarantees exp2 args <= 0. Per-column constants cancel:
//   dst_j = -ln2 * ( Mv + log2( sum_i 2^( u'_i + d_j + 2k r_i.q_j ) ) )
//   u'_i = (src_i+alpha)*log2e - k|r_i|^2  (packed into sR[i].w)
//   d_j  = -k|q_j|^2 - Mv
__device__ __forceinline__ void half_update(
    float4* __restrict__ sR, const float4* __restrict__ sQ,
    float* __restrict__ sRed,
    const float* __restrict__ src, float* __restrict__ dst,
    float* errslot, int slot)
{
    const int tid = threadIdx.x, wid = tid >> 5, lane = tid & 31;

    float lmax = -3.4e38f;
    for (int t = tid; t < NN; t += TPB) {
        float s  = __ldcg(src + t);
        float4 r = sR[t];
        float rr = fmaf(r.x, r.x, fmaf(r.y, r.y, r.z * r.z));
        float p  = (s + C_ALPHA) * C_L2E;
        lmax = fmaxf(lmax, p);
        sR[t].w = p - C_KK * rr;
    }
#pragma unroll
    for (int o = 16; o > 0; o >>= 1)
        lmax = fmaxf(lmax, __shfl_xor_sync(0xffffffffu, lmax, o));
    if (lane == 0) sRed[wid] = lmax;
    __syncthreads();
    if (wid == 0) {
        float v = (lane < WPC) ? sRed[lane] : -3.4e38f;
#pragma unroll
        for (int o = 16; o > 0; o >>= 1)
            v = fmaxf(v, __shfl_xor_sync(0xffffffffu, v, o));
        if (lane == 0) sRed[32] = v;
    }
    __syncthreads();
    const float Mv = sRed[32];

    const int j0 = (slot * WPC + wid) * TC;
    float qx[TC], qy[TC], qz[TC], dj[TC];
#pragma unroll
    for (int t = 0; t < TC; t++) {
        float4 q = sQ[j0 + t];
        float qq = fmaf(q.x, q.x, fmaf(q.y, q.y, q.z * q.z));
        qx[t] = q.x * C_2K; qy[t] = q.y * C_2K; qz[t] = q.z * C_2K;
        dj[t] = -C_KK * qq - Mv;
    }

    float sa[TC];
#pragma unroll
    for (int t = 0; t < TC; t++) sa[t] = 0.f;
#pragma unroll 4
    for (int i = lane; i < NN; i += 32) {
        float4 g = sR[i];
#pragma unroll
        for (int t = 0; t < TC; t++) {
            float w = fmaf(g.x, qx[t], fmaf(g.y, qy[t], fmaf(g.z, qz[t], g.w + dj[t])));
            sa[t] += ex2f_(w);
        }
    }
#pragma unroll
    for (int o = 16; o > 0; o >>= 1)
#pragma unroll
        for (int t = 0; t < TC; t++)
            sa[t] += __shfl_xor_sync(0xffffffffu, sa[t], o);

    if (lane == 0) {
        float esum = 0.f;
#pragma unroll
        for (int t = 0; t < TC; t++) {
            float s2 = fmaxf(sa[t], 1e-35f);
            float nv = -C_LN2 * (Mv + lg2f_(s2));
            float ov = __ldcg(dst + j0 + t);
            esum += fabsf(nv - ov);
            __stcg(dst + j0 + t, nv);
        }
        atomicAdd(errslot, esum);
    }
    // no trailing sync: caller's grid_barrier starts with __syncthreads
}

// cost = sum_ij exp(A_j + B_i - C_ij/eps) * C_ij  (accumulated; /(n*m) at end)
__device__ __forceinline__ void cost_pass(
    float4* __restrict__ sR, const float4* __restrict__ sQ,
    float* __restrict__ sAux,
    const float* __restrict__ srcRow, const float* __restrict__ srcCol,
    float* costslot, int slot)
{
    const int tid = threadIdx.x, wid = tid >> 5, lane = tid & 31;
    for (int t = tid; t < NN; t += TPB) {
        float s  = __ldcg(srcRow + t);
        float4 r = sR[t];
        float rr = fmaf(r.x, r.x, fmaf(r.y, r.y, r.z * r.z));
        sAux[t] = rr;
        sR[t].w = fmaf(s, C_L2E, -C_KK * rr);
    }
    __syncthreads();

    const int j0 = (slot * WPC + wid) * TC;
    float qx[TC], qy[TC], qz[TC], cp[TC], qw[TC];
#pragma unroll
    for (int t = 0; t < TC; t++) {
        float4 q = sQ[j0 + t];
        float qq = fmaf(q.x, q.x, fmaf(q.y, q.y, q.z * q.z));
        qx[t] = q.x * C_2K; qy[t] = q.y * C_2K; qz[t] = q.z * C_2K;
        qw[t] = qq;
        float a = __ldcg(srcCol + j0 + t);
        cp[t] = fmaf(a, C_L2E, -C_KK * qq);
    }

    float a1[TC], a2[TC];
#pragma unroll
    for (int t = 0; t < TC; t++) { a1[t] = 0.f; a2[t] = 0.f; }
#pragma unroll 2
    for (int i = lane; i < NN; i += 32) {
        float4 g = sR[i];
        float rr = sAux[i];
        float  u = g.w;
#pragma unroll
        for (int t = 0; t < TC; t++) {
            float w = fmaf(g.x, qx[t], fmaf(g.y, qy[t], fmaf(g.z, qz[t], u)));
            float e = ex2f_(w + cp[t]);
            float X = fmaf(u - w, C_INVK, rr);   // |r|^2 - 2 r.q
            a1[t] = fmaf(e, X, a1[t]);
            a2[t] += e;
        }
    }
#pragma unroll
    for (int o = 16; o > 0; o >>= 1)
#pragma unroll
        for (int t = 0; t < TC; t++) {
            a1[t] += __shfl_xor_sync(0xffffffffu, a1[t], o);
            a2[t] += __shfl_xor_sync(0xffffffffu, a2[t], o);
        }
    if (lane == 0) {
        float v = 0.f;
#pragma unroll
        for (int t = 0; t < TC; t++) v += a1[t] + qw[t] * a2[t];
        atomicAdd(costslot, v);
    }
    __syncthreads();
}

// chamfer: per own-point j (sOwn), min over iter-points i of |i - j|^2
__device__ __forceinline__ void cham_pass(
    const float4* __restrict__ sIter, const float4* __restrict__ sOwn,
    float* accum, int slot)
{
    const int tid = threadIdx.x, wid = tid >> 5, lane = tid & 31;
    const int j0 = (slot * WPC + wid) * TC;
    float qx[TC], qy[TC], qz[TC], qw[TC], m[TC];
#pragma unroll
    for (int t = 0; t < TC; t++) {
        float4 q = sOwn[j0 + t];
        qx[t] = -2.f * q.x; qy[t] = -2.f * q.y; qz[t] = -2.f * q.z;
        qw[t] = q.w;
        m[t] = 3.4e38f;
    }
#pragma unroll 4
    for (int i = lane; i < NN; i += 32) {
        float4 g = sIter[i];
#pragma unroll
        for (int t = 0; t < TC; t++) {
            float v = fmaf(g.x, qx[t], fmaf(g.y, qy[t], fmaf(g.z, qz[t], g.w)));
            m[t] = fminf(m[t], v);
        }
    }
#pragma unroll
    for (int o = 16; o > 0; o >>= 1)
#pragma unroll
        for (int t = 0; t < TC; t++)
            m[t] = fminf(m[t], __shfl_xor_sync(0xffffffffu, m[t], o));
    if (lane == 0) {
        float s = 0.f;
#pragma unroll
        for (int t = 0; t < TC; t++) s += m[t] + qw[t];
        atomicAdd(accum, s);
    }
    __syncthreads();
}

__device__ __forceinline__ void run_sink(
    float4* sRow, float4* sCol, float* sAux, float* sRed,
    float* A, float* Bv, int erroff, float* costslot, int b, int slot, unsigned& lb)
{
    int it = 0;
    bool cont = true;
    while (cont) {
        half_update(sRow, sCol, sRed, Bv, A, &g_s.errA[erroff + it * NB + b], slot);
        grid_barrier(lb);
        half_update(sCol, sRow, sRed, A, Bv, &g_s.errB[erroff + it * NB + b], slot);
        grid_barrier(lb);
        float ae = 0.f, be = 0.f;
#pragma unroll
        for (int bb = 0; bb < NB; bb++) {
            ae = fmaxf(ae, __ldcg(&g_s.errA[erroff + it * NB + bb]));
            be = fmaxf(be, __ldcg(&g_s.errB[erroff + it * NB + bb]));
        }
        ae *= (C_EPS / (float)NN);
        be *= (C_EPS / (float)NN);
        it++;
        cont = (it < NITS_K) && (ae >= C_TOL || be >= C_TOL);
    }
    cost_pass(sRow, sCol, sAux, Bv, A, costslot, slot);
}

__global__ void __launch_bounds__(TPB, 2)
emd_kernel(const float* __restrict__ preds, const float* __restrict__ gts,
           float* __restrict__ out, int out_size)
{
    extern __shared__ float4 smem4[];
    float4* sG   = smem4;                       // gts points (x,y,z,w)
    float4* sP   = smem4 + NN;                  // preds points
    float*  sAux = (float*)(smem4 + 2 * NN);    // |r|^2 during cost passes
    float*  sRed = sAux + NN;                   // 33+ floats reduction scratch

    const int b    = blockIdx.x >> 6;
    const int slot = blockIdx.x & 63;

    const float* gp = gts + (size_t)b * NN * 3;
    const float* pp = preds + (size_t)b * NN * 3;
    for (int i = threadIdx.x; i < NN; i += TPB) {
        float x = gp[3 * i + 0], y = gp[3 * i + 1], z = gp[3 * i + 2];
        sG[i] = make_float4(x, y, z, fmaf(x, x, fmaf(y, y, z * z)));
        x = pp[3 * i + 0]; y = pp[3 * i + 1]; z = pp[3 * i + 2];
        sP[i] = make_float4(x, y, z, fmaf(x, x, fmaf(y, y, z * z)));
    }
    __syncthreads();

    unsigned lb = 0;

    // Chamfer first (needs .w == |point|^2 before half_updates overwrite it)
    cham_pass(sG, sP, &g_s.cham[b], slot);
    cham_pass(sP, sG, &g_s.cham[NB + b], slot);

    // Sinkhorn run 1: C(gts, preds)
    run_sink(sG, sP, sAux, sRed, g_s.A1 + b * NN, g_s.B1 + b * NN,
             0, &g_s.cost[b], b, slot, lb);

    // Sinkhorn run 2: C(preds, preds)
    run_sink(sP, sP, sAux, sRed, g_s.A2 + b * NN, g_s.B2 + b * NN,
             NITS_K * NB, &g_s.cost[NB + b], b, slot, lb);

    grid_barrier(lb);

    if (blockIdx.x == 0 && threadIdx.x == 0) {
        const float inv_nm = 1.0f / ((float)NN * (float)NN);
        for (int bb = 0; bb < NB && bb < out_size; bb++) {
            float c1 = __ldcg(&g_s.cost[bb]);
            float c2 = __ldcg(&g_s.cost[NB + bb]);
            out[bb] = (c1 - 0.5f * c2) * inv_nm;
        }
        if (out_size >= 5) {
            float ch = 0.f;
            for (int bb = 0; bb < NB; bb++)
                ch += __ldcg(&g_s.cham[bb]) + __ldcg(&g_s.cham[NB + bb]);
            out[4] = ch / (float)(NB * NN);
        }
    }
}

extern "C" void kernel_launch(void* const* d_in, const int* in_sizes, int n_in,
                              void* d_out, int out_size)
{
    const float* preds = (const float*)d_in[0];
    const float* gts   = (const float*)d_in[1];
    float* out = (float*)d_out;

    void* sptr = nullptr;
    cudaGetSymbolAddress(&sptr, g_s);
    cudaMemsetAsync(sptr, 0, sizeof(ScratchT), 0);

    const int smem = (int)(2 * NN * sizeof(float4) + NN * sizeof(float) + 64 * sizeof(float));
    cudaFuncSetAttribute(emd_kernel, cudaFuncAttributeMaxDynamicSharedMemorySize, smem);
    emd_kernel<<<NCTA, TPB, smem, 0>>>(preds, gts, out, out_size);
}

// round 3
// speedup vs baseline: 2.2580x; 2.0983x over previous
#include <cuda_runtime.h>
#include <cstdint>
#include <cstddef>

#define NB 4
#define NN 2048
#define NCTA 256
#define TPB 512
#define NITS_K 50
#define TC 4

typedef unsigned long long u64;

constexpr float C_EPS  = 0.1f;
constexpr float C_TOL  = 1e-3f;
constexpr float C_L2E  = 1.4426950408889634f;
constexpr float C_KK   = C_L2E / C_EPS;          // log2(e)/eps
constexpr float C_2K   = 2.0f * C_KK;
constexpr float C_INVK = C_EPS / C_L2E;
constexpr float C_LN2  = 0.6931471805599453f;
constexpr float C_AL2E = -2.0f;                  // log2(1/4) = alpha*log2(e)

struct ScratchT {
    unsigned barcnt;
    unsigned pad[31];
    float AU[NB * NN];                // u'-transformed A potentials (reused across runs)
    float BU[NB * NN];                // u'-transformed B potentials
    float errA[2 * NITS_K * NB];
    float errB[2 * NITS_K * NB];
    unsigned mvA[2 * NITS_K * NB];    // encoded max of p over A-side writers
    unsigned mvB[2 * NITS_K * NB];
    float cost[2 * NB];
    float cham[2 * NB];
};
__device__ ScratchT g_s;

__device__ __forceinline__ float ex2f_(float x) {
    float y; asm("ex2.approx.ftz.f32 %0, %1;" : "=f"(y) : "f"(x)); return y;
}
__device__ __forceinline__ float lg2f_(float x) {
    float y; asm("lg2.approx.f32 %0, %1;" : "=f"(y) : "f"(x)); return y;
}
__device__ __forceinline__ u64 pk2(float lo, float hi) {
    u64 r; asm("mov.b64 %0, {%1, %2};" : "=l"(r) : "f"(lo), "f"(hi)); return r;
}
__device__ __forceinline__ void upk(u64 v, float& lo, float& hi) {
    asm("mov.b64 {%0, %1}, %2;" : "=f"(lo), "=f"(hi) : "l"(v));
}
__device__ __forceinline__ u64 pfma(u64 a, u64 b, u64 c) {
    u64 d; asm("fma.rn.f32x2 %0, %1, %2, %3;" : "=l"(d) : "l"(a), "l"(b), "l"(c)); return d;
}
__device__ __forceinline__ u64 padd(u64 a, u64 b) {
    u64 d; asm("add.rn.f32x2 %0, %1, %2;" : "=l"(d) : "l"(a), "l"(b)); return d;
}
// order-preserving float<->uint encoding for atomicMax (0 is below -inf)
__device__ __forceinline__ unsigned encf(float f) {
    unsigned u = __float_as_uint(f);
    return (u & 0x80000000u) ? ~u : (u | 0x80000000u);
}
__device__ __forceinline__ float decf(unsigned e) {
    return (e & 0x80000000u) ? __uint_as_float(e & 0x7fffffffu) : __uint_as_float(~e);
}

// grid barrier: all 256 CTAs co-resident (2/SM), monotonic counter
__device__ __forceinline__ void grid_barrier(unsigned& lb) {
    __syncthreads();
    lb++;
    if (threadIdx.x == 0) {
        unsigned target = lb * (unsigned)NCTA;
        asm volatile("red.release.gpu.global.add.u32 [%0], %1;"
                     :: "l"(&g_s.barcnt), "r"(1u) : "memory");
        unsigned v;
        while (true) {
            asm volatile("ld.acquire.gpu.global.u32 %0, [%1];"
                         : "=r"(v) : "l"(&g_s.barcnt) : "memory");
            if (v >= target) break;
            __nanosleep(64);
        }
    }
    __syncthreads();
}

// One Sinkhorn half-update, log2 domain, u'-form potentials:
//   stored value u'_j = (v_j + alpha)*log2e - k*|q_j|^2
//   dst potential v_j = -ln2*(Mv + log2 sum_i 2^(u'_i + 2k r_i.q_j - k|q_j|^2 - Mv))
//   Mv = max_i p_i, p_i = (v_i + alpha)*log2e  (maintained by writers via atomicMax)
__device__ void half_update(
    const float* rX, const float* rY, const float* rZ,   // summed cloud SoA (smem)
    const float* cX, const float* cY, const float* cZ,   // output cloud SoA (smem)
    float* sU, float* sPart,
    const float* srcU, float* dstU,
    const unsigned* mvSrc, unsigned* mvDst, float* errSlot,
    bool firstSrc, bool firstDst, int slot)
{
    const int tid = threadIdx.x;

    // phase 1: populate sU (pure copy unless first half of a run)
    if (firstSrc) {
        for (int t = tid; t < NN; t += TPB) {
            float x = rX[t], y = rY[t], z = rZ[t];
            sU[t] = C_AL2E - C_KK * fmaf(x, x, fmaf(y, y, z * z));
        }
    } else {
        for (int t = tid; t < NN; t += TPB) sU[t] = __ldcg(srcU + t);
    }
    const float Mv = firstSrc ? C_AL2E : decf(__ldcg(mvSrc));
    __syncthreads();

    const int wid = tid >> 5, lane = tid & 31;
    const int pr = wid >> 1, h = wid & 1;
    const int j0 = (slot * 8 + pr) * TC;

    u64 qx2[TC], qy2[TC], qz2[TC], dj2[TC];
    float qqv[TC];
#pragma unroll
    for (int t = 0; t < TC; t++) {
        float qx = cX[j0 + t], qy = cY[j0 + t], qz = cZ[j0 + t];
        float qq = fmaf(qx, qx, fmaf(qy, qy, qz * qz));
        qqv[t] = qq;
        float sx = qx * C_2K, sy = qy * C_2K, sz = qz * C_2K;
        float dj = -C_KK * qq - Mv;
        qx2[t] = pk2(sx, sx); qy2[t] = pk2(sy, sy); qz2[t] = pk2(sz, sz);
        dj2[t] = pk2(dj, dj);
    }

    u64 sa2[TC];
#pragma unroll
    for (int t = 0; t < TC; t++) sa2[t] = pk2(0.f, 0.f);

    const float2* pX = (const float2*)rX;
    const float2* pY = (const float2*)rY;
    const float2* pZ = (const float2*)rZ;
    const float2* pU = (const float2*)sU;
    int idx = h * (NN / 4) + lane;       // float2 index; each warp covers NN/2 elements
#pragma unroll 2
    for (int k = 0; k < NN / 128; k++, idx += 32) {
        float2 x2 = pX[idx], y2 = pY[idx], z2 = pZ[idx], u2 = pU[idx];
        u64 X2 = pk2(x2.x, x2.y), Y2 = pk2(y2.x, y2.y);
        u64 Z2 = pk2(z2.x, z2.y), U2 = pk2(u2.x, u2.y);
#pragma unroll
        for (int t = 0; t < TC; t++) {
            u64 w = padd(U2, dj2[t]);
            w = pfma(Z2, qz2[t], w);
            w = pfma(Y2, qy2[t], w);
            w = pfma(X2, qx2[t], w);
            float lo, hi; upk(w, lo, hi);
            sa2[t] = padd(sa2[t], pk2(ex2f_(lo), ex2f_(hi)));
        }
    }

    float sa[TC];
#pragma unroll
    for (int t = 0; t < TC; t++) { float lo, hi; upk(sa2[t], lo, hi); sa[t] = lo + hi; }
#pragma unroll
    for (int o = 16; o > 0; o >>= 1)
#pragma unroll
        for (int t = 0; t < TC; t++)
            sa[t] += __shfl_xor_sync(0xffffffffu, sa[t], o);

    if (h == 1 && lane == 0) {
#pragma unroll
        for (int t = 0; t < TC; t++) sPart[pr * TC + t] = sa[t];
    }
    __syncthreads();

    if (h == 0 && lane == 0) {
        float errsum = 0.f, pmax = -3.4e38f;
#pragma unroll
        for (int t = 0; t < TC; t++) {
            float s = fmaxf(sa[t] + sPart[pr * TC + t], 1e-35f);
            float L = Mv + lg2f_(s);
            float pnew = C_AL2E - L;                 // (v+alpha)*log2e
            float unew = pnew - C_KK * qqv[t];
            float pold = firstDst ? C_AL2E
                                  : (__ldcg(dstU + j0 + t) + C_KK * qqv[t]);
            errsum += fabsf(pnew - pold);
            __stcg(dstU + j0 + t, unew);
            pmax = fmaxf(pmax, pnew);
        }
        atomicAdd(errSlot, errsum * C_LN2);
        atomicMax(mvDst, encf(pmax));
    }
    // caller's grid_barrier provides the trailing sync
}

// cost = sum_ij exp(A_j + B_i - C_ij/eps) * C_ij (accumulated; /(n*m) at end)
__device__ void cost_pass(
    const float* rX, const float* rY, const float* rZ,
    const float* cX, const float* cY, const float* cZ,
    float* sU, float* sPart,
    const float* srcU, const float* srcColU,
    float* costslot, int slot)
{
    const int tid = threadIdx.x;
    for (int t = tid; t < NN; t += TPB)
        sU[t] = __ldcg(srcU + t) + 2.0f;     // u = B*l2e - k|r|^2 = u'B + 2
    __syncthreads();

    const int wid = tid >> 5, lane = tid & 31;
    const int pr = wid >> 1, h = wid & 1;
    const int j0 = (slot * 8 + pr) * TC;

    float qx[TC], qy[TC], qz[TC], cp[TC], qq[TC];
#pragma unroll
    for (int t = 0; t < TC; t++) {
        float x = cX[j0 + t], y = cY[j0 + t], z = cZ[j0 + t];
        qq[t] = fmaf(x, x, fmaf(y, y, z * z));
        qx[t] = x * C_2K; qy[t] = y * C_2K; qz[t] = z * C_2K;
        cp[t] = __ldcg(srcColU + j0 + t) + 2.0f;   // A*l2e - k|q|^2
    }

    float a1[TC], a2[TC];
#pragma unroll
    for (int t = 0; t < TC; t++) { a1[t] = 0.f; a2[t] = 0.f; }

    const float2* pX = (const float2*)rX;
    const float2* pY = (const float2*)rY;
    const float2* pZ = (const float2*)rZ;
    const float2* pU = (const float2*)sU;
    int idx = h * (NN / 4) + lane;
    for (int k = 0; k < NN / 128; k++, idx += 32) {
        float2 x2 = pX[idx], y2 = pY[idx], z2 = pZ[idx], u2 = pU[idx];
#pragma unroll
        for (int e = 0; e < 2; e++) {
            float x = e ? x2.y : x2.x, y = e ? y2.y : y2.x;
            float z = e ? z2.y : z2.x, u = e ? u2.y : u2.x;
            float rr = fmaf(x, x, fmaf(y, y, z * z));
#pragma unroll
            for (int t = 0; t < TC; t++) {
                float w = fmaf(x, qx[t], fmaf(y, qy[t], fmaf(z, qz[t], u)));
                float ev = ex2f_(w + cp[t]);
                float Xv = fmaf(u - w, C_INVK, rr);   // |r|^2 - 2 r.q
                a1[t] = fmaf(ev, Xv, a1[t]);
                a2[t] += ev;
            }
        }
    }
#pragma unroll
    for (int o = 16; o > 0; o >>= 1)
#pragma unroll
        for (int t = 0; t < TC; t++) {
            a1[t] += __shfl_xor_sync(0xffffffffu, a1[t], o);
            a2[t] += __shfl_xor_sync(0xffffffffu, a2[t], o);
        }
    if (h == 1 && lane == 0) {
#pragma unroll
        for (int t = 0; t < TC; t++) {
            sPart[pr * 8 + t] = a1[t];
            sPart[pr * 8 + 4 + t] = a2[t];
        }
    }
    __syncthreads();
    if (h == 0 && lane == 0) {
        float v = 0.f;
#pragma unroll
        for (int t = 0; t < TC; t++) {
            float A1 = a1[t] + sPart[pr * 8 + t];
            float A2 = a2[t] + sPart[pr * 8 + 4 + t];
            v += A1 + qq[t] * A2;
        }
        atomicAdd(costslot, v);
    }
    __syncthreads();
}

// chamfer: per own-point j, min over iter-points i of |r_i - q_j|^2
__device__ void cham_pass(
    const float* iX, const float* iY, const float* iZ,
    const float* oX, const float* oY, const float* oZ,
    float* sPart, float* accum, int slot)
{
    const int tid = threadIdx.x, wid = tid >> 5, lane = tid & 31;
    const int pr = wid >> 1, h = wid & 1;
    const int j0 = (slot * 8 + pr) * TC;

    float qx[TC], qy[TC], qz[TC], qq[TC], m[TC];
#pragma unroll
    for (int t = 0; t < TC; t++) {
        float x = oX[j0 + t], y = oY[j0 + t], z = oZ[j0 + t];
        qq[t] = fmaf(x, x, fmaf(y, y, z * z));
        qx[t] = -2.f * x; qy[t] = -2.f * y; qz[t] = -2.f * z;
        m[t] = 3.4e38f;
    }
    const float2* pX = (const float2*)iX;
    const float2* pY = (const float2*)iY;
    const float2* pZ = (const float2*)iZ;
    int idx = h * (NN / 4) + lane;
    for (int k = 0; k < NN / 128; k++, idx += 32) {
        float2 x2 = pX[idx], y2 = pY[idx], z2 = pZ[idx];
#pragma unroll
        for (int e = 0; e < 2; e++) {
            float x = e ? x2.y : x2.x, y = e ? y2.y : y2.x, z = e ? z2.y : z2.x;
            float rr = fmaf(x, x, fmaf(y, y, z * z));
#pragma unroll
            for (int t = 0; t < TC; t++) {
                float v = fmaf(x, qx[t], fmaf(y, qy[t], fmaf(z, qz[t], rr)));
                m[t] = fminf(m[t], v);
            }
        }
    }
#pragma unroll
    for (int o = 16; o > 0; o >>= 1)
#pragma unroll
        for (int t = 0; t < TC; t++)
            m[t] = fminf(m[t], __shfl_xor_sync(0xffffffffu, m[t], o));
    if (h == 1 && lane == 0) {
#pragma unroll
        for (int t = 0; t < TC; t++) sPart[pr * TC + t] = m[t];
    }
    __syncthreads();
    if (h == 0 && lane == 0) {
        float s = 0.f;
#pragma unroll
        for (int t = 0; t < TC; t++)
            s += fminf(m[t], sPart[pr * TC + t]) + qq[t];
        atomicAdd(accum, s);
    }
    __syncthreads();
}

__device__ void run_sink(
    const float* rX, const float* rY, const float* rZ,   // rows (summed in A-half)
    const float* cX, const float* cY, const float* cZ,   // cols (output of A-half)
    float* sU, float* sPart,
    float* AU, float* BU, int off, float* costslot, int b, int slot, unsigned& lb)
{
    int it = 0;
    bool cont = true;
    while (cont) {
        // A-half: sum over rows, write A (cols)
        half_update(rX, rY, rZ, cX, cY, cZ, sU, sPart,
                    BU, AU,
                    &g_s.mvB[off + (it == 0 ? 0 : (it - 1) * NB) + b],
                    &g_s.mvA[off + it * NB + b],
                    &g_s.errA[off + it * NB + b],
                    it == 0, it == 0, slot);
        grid_barrier(lb);
        // B-half: sum over cols, write B (rows)
        half_update(cX, cY, cZ, rX, rY, rZ, sU, sPart,
                    AU, BU,
                    &g_s.mvA[off + it * NB + b],
                    &g_s.mvB[off + it * NB + b],
                    &g_s.errB[off + it * NB + b],
                    false, it == 0, slot);
        grid_barrier(lb);
        float ae = 0.f, be = 0.f;
#pragma unroll
        for (int bb = 0; bb < NB; bb++) {
            ae = fmaxf(ae, __ldcg(&g_s.errA[off + it * NB + bb]));
            be = fmaxf(be, __ldcg(&g_s.errB[off + it * NB + bb]));
        }
        ae *= (C_EPS / (float)NN);
        be *= (C_EPS / (float)NN);
        it++;
        cont = (it < NITS_K) && (ae >= C_TOL || be >= C_TOL);
    }
    cost_pass(rX, rY, rZ, cX, cY, cZ, sU, sPart, BU, AU, costslot, slot);
}

__global__ void __launch_bounds__(TPB, 2)
emd_kernel(const float* __restrict__ preds, const float* __restrict__ gts,
           float* __restrict__ out, int out_size)
{
    extern __shared__ float sm[];
    float* sGX = sm;            float* sGY = sm + NN;     float* sGZ = sm + 2 * NN;
    float* sPX = sm + 3 * NN;   float* sPY = sm + 4 * NN; float* sPZ = sm + 5 * NN;
    float* sU  = sm + 6 * NN;
    float* sPart = sm + 7 * NN;   // 64+ floats

    const int b    = blockIdx.x >> 6;
    const int slot = blockIdx.x & 63;

    const float* gp = gts + (size_t)b * NN * 3;
    const float* pp = preds + (size_t)b * NN * 3;
    for (int i = threadIdx.x; i < NN; i += TPB) {
        sGX[i] = gp[3 * i + 0]; sGY[i] = gp[3 * i + 1]; sGZ[i] = gp[3 * i + 2];
        sPX[i] = pp[3 * i + 0]; sPY[i] = pp[3 * i + 1]; sPZ[i] = pp[3 * i + 2];
    }
    __syncthreads();

    unsigned lb = 0;

    // chamfer: min over gts per pred, and min over preds per gt
    cham_pass(sGX, sGY, sGZ, sPX, sPY, sPZ, sPart, &g_s.cham[b], slot);
    cham_pass(sPX, sPY, sPZ, sGX, sGY, sGZ, sPart, &g_s.cham[NB + b], slot);

    // run 1: C(gts, preds) — rows = gts, cols = preds
    run_sink(sGX, sGY, sGZ, sPX, sPY, sPZ, sU, sPart,
             g_s.AU + b * NN, g_s.BU + b * NN, 0, &g_s.cost[b], b, slot, lb);

    // run 2: C(preds, preds)
    run_sink(sPX, sPY, sPZ, sPX, sPY, sPZ, sU, sPart,
             g_s.AU + b * NN, g_s.BU + b * NN, NITS_K * NB, &g_s.cost[NB + b], b, slot, lb);

    grid_barrier(lb);

    if (blockIdx.x == 0 && threadIdx.x == 0) {
        const float inv_nm = 1.0f / ((float)NN * (float)NN);
        for (int bb = 0; bb < NB && bb < out_size; bb++) {
            float c1 = __ldcg(&g_s.cost[bb]);
            float c2 = __ldcg(&g_s.cost[NB + bb]);
            out[bb] = (c1 - 0.5f * c2) * inv_nm;
        }
        if (out_size >= 5) {
            float ch = 0.f;
            for (int bb = 0; bb < NB; bb++)
                ch += __ldcg(&g_s.cham[bb]) + __ldcg(&g_s.cham[NB + bb]);
            out[4] = ch / (float)(NB * NN);
        }
    }
}

extern "C" void kernel_launch(void* const* d_in, const int* in_sizes, int n_in,
                              void* d_out, int out_size)
{
    const float* preds = (const float*)d_in[0];
    const float* gts   = (const float*)d_in[1];
    float* out = (float*)d_out;

    void* sptr = nullptr;
    cudaGetSymbolAddress(&sptr, g_s);
    cudaMemsetAsync(sptr, 0, sizeof(ScratchT), 0);

    const int smem = (int)((7 * NN + 128) * sizeof(float));
    cudaFuncSetAttribute(emd_kernel, cudaFuncAttributeMaxDynamicSharedMemorySize, smem);
    emd_kernel<<<NCTA, TPB, smem, 0>>>(preds, gts, out, out_size);
}

// round 4
// speedup vs baseline: 2.2653x; 1.0032x over previous
#include <cuda_runtime.h>
#include <cstdint>
#include <cstddef>

#define NB 4
#define NN 2048
#define NCTA 256
#define TPB 512
#define NITS_K 50
#define TC 4

typedef unsigned long long u64;

constexpr float C_EPS  = 0.1f;
constexpr float C_TOL  = 1e-3f;
constexpr float C_L2E  = 1.4426950408889634f;
constexpr float C_KK   = C_L2E / C_EPS;          // log2(e)/eps
constexpr float C_2K   = 2.0f * C_KK;
constexpr float C_INVK = C_EPS / C_L2E;
constexpr float C_LN2  = 0.6931471805599453f;
constexpr float C_AL2E = -2.0f;                  // log2(1/4) = alpha*log2(e)

struct ScratchT {
    unsigned barcnt;
    unsigned pad[31];
    float AU[NB * NN];                // u'-transformed A potentials (reused across runs)
    float BU[NB * NN];                // u'-transformed B potentials
    float errA[2 * NITS_K * NB];
    float errB[2 * NITS_K * NB];
    unsigned mvA[2 * NITS_K * NB];    // encoded max of p over A-side writers
    unsigned mvB[2 * NITS_K * NB];
    float cost[2 * NB];
    float cham[2 * NB];
};
__device__ ScratchT g_s;

__device__ __forceinline__ float ex2f_(float x) {
    float y; asm("ex2.approx.ftz.f32 %0, %1;" : "=f"(y) : "f"(x)); return y;
}
__device__ __forceinline__ float lg2f_(float x) {
    float y; asm("lg2.approx.f32 %0, %1;" : "=f"(y) : "f"(x)); return y;
}
__device__ __forceinline__ u64 pk2(float lo, float hi) {
    u64 r; asm("mov.b64 %0, {%1, %2};" : "=l"(r) : "f"(lo), "f"(hi)); return r;
}
__device__ __forceinline__ void upk(u64 v, float& lo, float& hi) {
    asm("mov.b64 {%0, %1}, %2;" : "=f"(lo), "=f"(hi) : "l"(v));
}
__device__ __forceinline__ u64 pfma(u64 a, u64 b, u64 c) {
    u64 d; asm("fma.rn.f32x2 %0, %1, %2, %3;" : "=l"(d) : "l"(a), "l"(b), "l"(c)); return d;
}
__device__ __forceinline__ u64 padd(u64 a, u64 b) {
    u64 d; asm("add.rn.f32x2 %0, %1, %2;" : "=l"(d) : "l"(a), "l"(b)); return d;
}
// order-preserving float<->uint encoding for atomicMax (0 is below -inf)
__device__ __forceinline__ unsigned encf(float f) {
    unsigned u = __float_as_uint(f);
    return (u & 0x80000000u) ? ~u : (u | 0x80000000u);
}
__device__ __forceinline__ float decf(unsigned e) {
    return (e & 0x80000000u) ? __uint_as_float(e & 0x7fffffffu) : __uint_as_float(~e);
}

// grid barrier: all 256 CTAs co-resident (2/SM), monotonic counter
__device__ __forceinline__ void grid_barrier(unsigned& lb) {
    __syncthreads();
    lb++;
    if (threadIdx.x == 0) {
        unsigned target = lb * (unsigned)NCTA;
        asm volatile("red.release.gpu.global.add.u32 [%0], %1;"
                     :: "l"(&g_s.barcnt), "r"(1u) : "memory");
        unsigned v;
        while (true) {
            asm volatile("ld.acquire.gpu.global.u32 %0, [%1];"
                         : "=r"(v) : "l"(&g_s.barcnt) : "memory");
            if (v >= target) break;
            __nanosleep(64);
        }
    }
    __syncthreads();
}

// One Sinkhorn half-update, log2 domain, u'-form potentials:
//   stored value u'_j = (v_j + alpha)*log2e - k*|q_j|^2
//   dst potential v_j = -ln2*(Mv + log2 sum_i 2^(u'_i + 2k r_i.q_j - k|q_j|^2 - Mv))
//   Mv = max_i p_i, p_i = (v_i + alpha)*log2e  (maintained by writers via atomicMax)
__device__ void half_update(
    const float* rX, const float* rY, const float* rZ,   // summed cloud SoA (smem)
    const float* cX, const float* cY, const float* cZ,   // output cloud SoA (smem)
    float* sU, float* sPart,
    const float* srcU, float* dstU,
    const unsigned* mvSrc, unsigned* mvDst, float* errSlot,
    bool firstSrc, bool firstDst, int slot)
{
    const int tid = threadIdx.x;

    // phase 1: populate sU (pure copy unless first half of a run)
    if (firstSrc) {
        for (int t = tid; t < NN; t += TPB) {
            float x = rX[t], y = rY[t], z = rZ[t];
            sU[t] = C_AL2E - C_KK * fmaf(x, x, fmaf(y, y, z * z));
        }
    } else {
        for (int t = tid; t < NN; t += TPB) sU[t] = __ldcg(srcU + t);
    }
    const float Mv = firstSrc ? C_AL2E : decf(__ldcg(mvSrc));
    __syncthreads();

    const int wid = tid >> 5, lane = tid & 31;
    const int pr = wid >> 1, h = wid & 1;
    const int j0 = (slot * 8 + pr) * TC;

    u64 qx2[TC], qy2[TC], qz2[TC], dj2[TC];
    float qqv[TC];
#pragma unroll
    for (int t = 0; t < TC; t++) {
        float qx = cX[j0 + t], qy = cY[j0 + t], qz = cZ[j0 + t];
        float qq = fmaf(qx, qx, fmaf(qy, qy, qz * qz));
        qqv[t] = qq;
        float sx = qx * C_2K, sy = qy * C_2K, sz = qz * C_2K;
        float dj = -C_KK * qq - Mv;
        qx2[t] = pk2(sx, sx); qy2[t] = pk2(sy, sy); qz2[t] = pk2(sz, sz);
        dj2[t] = pk2(dj, dj);
    }

    u64 sa2[TC];
#pragma unroll
    for (int t = 0; t < TC; t++) sa2[t] = pk2(0.f, 0.f);

    const float2* pX = (const float2*)rX;
    const float2* pY = (const float2*)rY;
    const float2* pZ = (const float2*)rZ;
    const float2* pU = (const float2*)sU;
    int idx = h * (NN / 4) + lane;       // float2 index; each warp covers NN/2 elements
#pragma unroll 2
    for (int k = 0; k < NN / 128; k++, idx += 32) {
        float2 x2 = pX[idx], y2 = pY[idx], z2 = pZ[idx], u2 = pU[idx];
        u64 X2 = pk2(x2.x, x2.y), Y2 = pk2(y2.x, y2.y);
        u64 Z2 = pk2(z2.x, z2.y), U2 = pk2(u2.x, u2.y);
#pragma unroll
        for (int t = 0; t < TC; t++) {
            u64 w = padd(U2, dj2[t]);
            w = pfma(Z2, qz2[t], w);
            w = pfma(Y2, qy2[t], w);
            w = pfma(X2, qx2[t], w);
            float lo, hi; upk(w, lo, hi);
            sa2[t] = padd(sa2[t], pk2(ex2f_(lo), ex2f_(hi)));
        }
    }

    float sa[TC];
#pragma unroll
    for (int t = 0; t < TC; t++) { float lo, hi; upk(sa2[t], lo, hi); sa[t] = lo + hi; }
#pragma unroll
    for (int o = 16; o > 0; o >>= 1)
#pragma unroll
        for (int t = 0; t < TC; t++)
            sa[t] += __shfl_xor_sync(0xffffffffu, sa[t], o);

    if (h == 1 && lane == 0) {
#pragma unroll
        for (int t = 0; t < TC; t++) sPart[pr * TC + t] = sa[t];
    }
    __syncthreads();

    if (h == 0 && lane == 0) {
        float errsum = 0.f, pmax = -3.4e38f;
#pragma unroll
        for (int t = 0; t < TC; t++) {
            float s = fmaxf(sa[t] + sPart[pr * TC + t], 1e-35f);
            float L = Mv + lg2f_(s);
            float pnew = C_AL2E - L;                 // (v+alpha)*log2e
            float unew = pnew - C_KK * qqv[t];
            float pold = firstDst ? C_AL2E
                                  : (__ldcg(dstU + j0 + t) + C_KK * qqv[t]);
            errsum += fabsf(pnew - pold);
            __stcg(dstU + j0 + t, unew);
            pmax = fmaxf(pmax, pnew);
        }
        atomicAdd(errSlot, errsum * C_LN2);
        atomicMax(mvDst, encf(pmax));
    }
    // caller's grid_barrier provides the trailing sync
}

// cost = sum_ij exp(A_j + B_i - C_ij/eps) * C_ij (accumulated; /(n*m) at end)
__device__ void cost_pass(
    const float* rX, const float* rY, const float* rZ,
    const float* cX, const float* cY, const float* cZ,
    float* sU, float* sPart,
    const float* srcU, const float* srcColU,
    float* costslot, int slot)
{
    const int tid = threadIdx.x;
    for (int t = tid; t < NN; t += TPB)
        sU[t] = __ldcg(srcU + t) + 2.0f;     // u = B*l2e - k|r|^2 = u'B + 2
    __syncthreads();

    const int wid = tid >> 5, lane = tid & 31;
    const int pr = wid >> 1, h = wid & 1;
    const int j0 = (slot * 8 + pr) * TC;

    float qx[TC], qy[TC], qz[TC], cp[TC], qq[TC];
#pragma unroll
    for (int t = 0; t < TC; t++) {
        float x = cX[j0 + t], y = cY[j0 + t], z = cZ[j0 + t];
        qq[t] = fmaf(x, x, fmaf(y, y, z * z));
        qx[t] = x * C_2K; qy[t] = y * C_2K; qz[t] = z * C_2K;
        cp[t] = __ldcg(srcColU + j0 + t) + 2.0f;   // A*l2e - k|q|^2
    }

    float a1[TC], a2[TC];
#pragma unroll
    for (int t = 0; t < TC; t++) { a1[t] = 0.f; a2[t] = 0.f; }

    const float2* pX = (const float2*)rX;
    const float2* pY = (const float2*)rY;
    const float2* pZ = (const float2*)rZ;
    const float2* pU = (const float2*)sU;
    int idx = h * (NN / 4) + lane;
    for (int k = 0; k < NN / 128; k++, idx += 32) {
        float2 x2 = pX[idx], y2 = pY[idx], z2 = pZ[idx], u2 = pU[idx];
#pragma unroll
        for (int e = 0; e < 2; e++) {
            float x = e ? x2.y : x2.x, y = e ? y2.y : y2.x;
            float z = e ? z2.y : z2.x, u = e ? u2.y : u2.x;
            float rr = fmaf(x, x, fmaf(y, y, z * z));
#pragma unroll
            for (int t = 0; t < TC; t++) {
                float w = fmaf(x, qx[t], fmaf(y, qy[t], fmaf(z, qz[t], u)));
                float ev = ex2f_(w + cp[t]);
                float Xv = fmaf(u - w, C_INVK, rr);   // |r|^2 - 2 r.q
                a1[t] = fmaf(ev, Xv, a1[t]);
                a2[t] += ev;
            }
        }
    }
#pragma unroll
    for (int o = 16; o > 0; o >>= 1)
#pragma unroll
        for (int t = 0; t < TC; t++) {
            a1[t] += __shfl_xor_sync(0xffffffffu, a1[t], o);
            a2[t] += __shfl_xor_sync(0xffffffffu, a2[t], o);
        }
    if (h == 1 && lane == 0) {
#pragma unroll
        for (int t = 0; t < TC; t++) {
            sPart[pr * 8 + t] = a1[t];
            sPart[pr * 8 + 4 + t] = a2[t];
        }
    }
    __syncthreads();
    if (h == 0 && lane == 0) {
        float v = 0.f;
#pragma unroll
        for (int t = 0; t < TC; t++) {
            float A1 = a1[t] + sPart[pr * 8 + t];
            float A2 = a2[t] + sPart[pr * 8 + 4 + t];
            v += A1 + qq[t] * A2;
        }
        atomicAdd(costslot, v);
    }
    __syncthreads();
}

// chamfer: per own-point j, min over iter-points i of |r_i - q_j|^2
__device__ void cham_pass(
    const float* iX, const float* iY, const float* iZ,
    const float* oX, const float* oY, const float* oZ,
    float* sPart, float* accum, int slot)
{
    const int tid = threadIdx.x, wid = tid >> 5, lane = tid & 31;
    const int pr = wid >> 1, h = wid & 1;
    const int j0 = (slot * 8 + pr) * TC;

    float qx[TC], qy[TC], qz[TC], qq[TC], m[TC];
#pragma unroll
    for (int t = 0; t < TC; t++) {
        float x = oX[j0 + t], y = oY[j0 + t], z = oZ[j0 + t];
        qq[t] = fmaf(x, x, fmaf(y, y, z * z));
        qx[t] = -2.f * x; qy[t] = -2.f * y; qz[t] = -2.f * z;
        m[t] = 3.4e38f;
    }
    const float2* pX = (const float2*)iX;
    const float2* pY = (const float2*)iY;
    const float2* pZ = (const float2*)iZ;
    int idx = h * (NN / 4) + lane;
    for (int k = 0; k < NN / 128; k++, idx += 32) {
        float2 x2 = pX[idx], y2 = pY[idx], z2 = pZ[idx];
#pragma unroll
        for (int e = 0; e < 2; e++) {
            float x = e ? x2.y : x2.x, y = e ? y2.y : y2.x, z = e ? z2.y : z2.x;
            float rr = fmaf(x, x, fmaf(y, y, z * z));
#pragma unroll
            for (int t = 0; t < TC; t++) {
                float v = fmaf(x, qx[t], fmaf(y, qy[t], fmaf(z, qz[t], rr)));
                m[t] = fminf(m[t], v);
            }
        }
    }
#pragma unroll
    for (int o = 16; o > 0; o >>= 1)
#pragma unroll
        for (int t = 0; t < TC; t++)
            m[t] = fminf(m[t], __shfl_xor_sync(0xffffffffu, m[t], o));
    if (h == 1 && lane == 0) {
#pragma unroll
        for (int t = 0; t < TC; t++) sPart[pr * TC + t] = m[t];
    }
    __syncthreads();
    if (h == 0 && lane == 0) {
        float s = 0.f;
#pragma unroll
        for (int t = 0; t < TC; t++)
            s += fminf(m[t], sPart[pr * TC + t]) + qq[t];
        atomicAdd(accum, s);
    }
    __syncthreads();
}

__device__ void run_sink(
    const float* rX, const float* rY, const float* rZ,   // rows (summed in A-half)
    const float* cX, const float* cY, const float* cZ,   // cols (output of A-half)
    float* sU, float* sPart,
    float* AU, float* BU, int off, float* costslot, int b, int slot, unsigned& lb)
{
    int it = 0;
    bool cont = true;
    while (cont) {
        // A-half: sum over rows, write A (cols)
        half_update(rX, rY, rZ, cX, cY, cZ, sU, sPart,
                    BU, AU,
                    &g_s.mvB[off + (it == 0 ? 0 : (it - 1) * NB) + b],
                    &g_s.mvA[off + it * NB + b],
                    &g_s.errA[off + it * NB + b],
                    it == 0, it == 0, slot);
        grid_barrier(lb);
        // B-half: sum over cols, write B (rows)
        half_update(cX, cY, cZ, rX, rY, rZ, sU, sPart,
                    AU, BU,
                    &g_s.mvA[off + it * NB + b],
                    &g_s.mvB[off + it * NB + b],
                    &g_s.errB[off + it * NB + b],
                    false, it == 0, slot);
        grid_barrier(lb);
        float ae = 0.f, be = 0.f;
#pragma unroll
        for (int bb = 0; bb < NB; bb++) {
            ae = fmaxf(ae, __ldcg(&g_s.errA[off + it * NB + bb]));
            be = fmaxf(be, __ldcg(&g_s.errB[off + it * NB + bb]));
        }
        ae *= (C_EPS / (float)NN);
        be *= (C_EPS / (float)NN);
        it++;
        cont = (it < NITS_K) && (ae >= C_TOL || be >= C_TOL);
    }
    cost_pass(rX, rY, rZ, cX, cY, cZ, sU, sPart, BU, AU, costslot, slot);
}

__global__ void __launch_bounds__(TPB, 2)
emd_kernel(const float* __restrict__ preds, const float* __restrict__ gts,
           float* __restrict__ out, int out_size)
{
    extern __shared__ float sm[];
    float* sGX = sm;            float* sGY = sm + NN;     float* sGZ = sm + 2 * NN;
    float* sPX = sm + 3 * NN;   float* sPY = sm + 4 * NN; float* sPZ = sm + 5 * NN;
    float* sU  = sm + 6 * NN;
    float* sPart = sm + 7 * NN;   // 64+ floats

    const int b    = blockIdx.x >> 6;
    const int slot = blockIdx.x & 63;

    const float* gp = gts + (size_t)b * NN * 3;
    const float* pp = preds + (size_t)b * NN * 3;
    for (int i = threadIdx.x; i < NN; i += TPB) {
        sGX[i] = gp[3 * i + 0]; sGY[i] = gp[3 * i + 1]; sGZ[i] = gp[3 * i + 2];
        sPX[i] = pp[3 * i + 0]; sPY[i] = pp[3 * i + 1]; sPZ[i] = pp[3 * i + 2];
    }
    __syncthreads();

    unsigned lb = 0;

    // chamfer: min over gts per pred, and min over preds per gt
    cham_pass(sGX, sGY, sGZ, sPX, sPY, sPZ, sPart, &g_s.cham[b], slot);
    cham_pass(sPX, sPY, sPZ, sGX, sGY, sGZ, sPart, &g_s.cham[NB + b], slot);

    // run 1: C(gts, preds) — rows = gts, cols = preds
    run_sink(sGX, sGY, sGZ, sPX, sPY, sPZ, sU, sPart,
             g_s.AU + b * NN, g_s.BU + b * NN, 0, &g_s.cost[b], b, slot, lb);

    // run 2: C(preds, preds)
    run_sink(sPX, sPY, sPZ, sPX, sPY, sPZ, sU, sPart,
             g_s.AU + b * NN, g_s.BU + b * NN, NITS_K * NB, &g_s.cost[NB + b], b, slot, lb);

    grid_barrier(lb);

    if (blockIdx.x == 0 && threadIdx.x == 0) {
        const float inv_nm = 1.0f / ((float)NN * (float)NN);
        for (int bb = 0; bb < NB && bb < out_size; bb++) {
            float c1 = __ldcg(&g_s.cost[bb]);
            float c2 = __ldcg(&g_s.cost[NB + bb]);
            out[bb] = (c1 - 0.5f * c2) * inv_nm;
        }
        if (out_size >= 5) {
            float ch = 0.f;
            for (int bb = 0; bb < NB; bb++)
                ch += __ldcg(&g_s.cham[bb]) + __ldcg(&g_s.cham[NB + bb]);
            out[4] = ch / (float)(NB * NN);
        }
    }
}

extern "C" void kernel_launch(void* const* d_in, const int* in_sizes, int n_in,
                              void* d_out, int out_size)
{
    const float* preds = (const float*)d_in[0];
    const float* gts   = (const float*)d_in[1];
    float* out = (float*)d_out;

    void* sptr = nullptr;
    cudaGetSymbolAddress(&sptr, g_s);
    cudaMemsetAsync(sptr, 0, sizeof(ScratchT), 0);

    const int smem = (int)((7 * NN + 128) * sizeof(float));
    cudaFuncSetAttribute(emd_kernel, cudaFuncAttributeMaxDynamicSharedMemorySize, smem);
    emd_kernel<<<NCTA, TPB, smem, 0>>>(preds, gts, out, out_size);
}